// round 1
// baseline (speedup 1.0000x reference)
#include <cuda_runtime.h>

// Problem constants
#define BB 8
#define NN 8192
#define DD 256
#define NSPLIT 32          // split-K for lambda GEMM
#define TOTROWS (BB*NN)    // 65536

// ---------------- scratch (static device globals; no allocs allowed) -------
__device__ float g_Q[TOTROWS*DD];          // 67 MB
__device__ float g_K[TOTROWS*DD];          // 67 MB (becomes P after k_norm)
__device__ float g_V[TOTROWS*DD];          // 67 MB
__device__ float g_colmax[BB*DD];
__device__ float g_colrcp[BB*DD];
__device__ float g_lampart[NSPLIT*BB*DD*DD];  // 67 MB
__device__ float g_lam[BB*DD*DD];          // 2 MB
__device__ float g_scale[DD];
__device__ float g_shift[DD];
__device__ float g_bn[BB*DD*DD];           // 2 MB

// ---------------- FMA-only exp (avoids MUFU throughput wall) ---------------
__device__ __forceinline__ float fexp(float x) {
    float y = x * 1.4426950408889634f;       // x * log2(e)
    y = fmaxf(y, -126.0f);
    float r = rintf(y);
    float f = y - r;                          // f in [-0.5, 0.5]
    float t = f * 0.6931471805599453f;        // t in [-0.347, 0.347]
    float p = 1.3888889e-3f;                  // 1/720
    p = fmaf(p, t, 8.3333333e-3f);            // 1/120
    p = fmaf(p, t, 4.1666667e-2f);            // 1/24
    p = fmaf(p, t, 1.6666667e-1f);            // 1/6
    p = fmaf(p, t, 0.5f);
    p = fmaf(p, t, 1.0f);
    p = fmaf(p, t, 1.0f);
    float sc = __int_as_float(((int)r + 127) << 23);
    return p * sc;
}

// ---------------- Kernel 1: fused QKV GEMM ---------------------------------
// C[65536 x 768] = X[65536 x 256] * [Wq | Wk | Wv] + bias, scattered to Q/K/V
__global__ __launch_bounds__(256) void k_qkv(
    const float* __restrict__ X, const float* __restrict__ Wqk,
    const float* __restrict__ bqk, const float* __restrict__ Wv,
    const float* __restrict__ bv)
{
    __shared__ float As[16][128];
    __shared__ float Bs[16][128];

    int n0 = blockIdx.x * 128;     // [0,768)
    int m0 = blockIdx.y * 128;     // [0,65536)
    int which = n0 >> 8;
    int c0 = n0 & 255;
    const float* Wb; const float* bb; float* Cb;
    if (which == 0)      { Wb = Wqk;           bb = bqk;       Cb = g_Q; }
    else if (which == 1) { Wb = Wqk + DD*DD;   bb = bqk + DD;  Cb = g_K; }
    else                 { Wb = Wv;            bb = bv;        Cb = g_V; }

    int tid = threadIdx.x;
    int tx = tid & 15, ty = tid >> 4;
    float acc[8][8];
    #pragma unroll
    for (int i = 0; i < 8; i++)
        #pragma unroll
        for (int j = 0; j < 8; j++) acc[i][j] = 0.f;

    for (int kk = 0; kk < 256; kk += 16) {
        // A tile: 128 rows x 16 cols, transposed into As[k][m]
        #pragma unroll
        for (int i = 0; i < 2; i++) {
            int f = tid + i * 256;
            int r = f >> 2, c4 = (f & 3) * 4;
            float4 v = *(const float4*)&X[(m0 + r) * 256 + kk + c4];
            As[c4+0][r] = v.x; As[c4+1][r] = v.y;
            As[c4+2][r] = v.z; As[c4+3][r] = v.w;
        }
        // B tile: 16 rows x 128 cols, direct
        #pragma unroll
        for (int i = 0; i < 2; i++) {
            int f = tid + i * 256;
            int r = f >> 5, c4 = (f & 31) * 4;
            *(float4*)&Bs[r][c4] = *(const float4*)&Wb[(kk + r) * 256 + c0 + c4];
        }
        __syncthreads();
        #pragma unroll
        for (int k = 0; k < 16; k++) {
            float a[8], b[8];
            *(float4*)&a[0] = *(float4*)&As[k][ty*8];
            *(float4*)&a[4] = *(float4*)&As[k][ty*8+4];
            *(float4*)&b[0] = *(float4*)&Bs[k][tx*8];
            *(float4*)&b[4] = *(float4*)&Bs[k][tx*8+4];
            #pragma unroll
            for (int i = 0; i < 8; i++)
                #pragma unroll
                for (int j = 0; j < 8; j++)
                    acc[i][j] = fmaf(a[i], b[j], acc[i][j]);
        }
        __syncthreads();
    }
    #pragma unroll
    for (int i = 0; i < 8; i++) {
        int r = m0 + ty*8 + i;
        #pragma unroll
        for (int j = 0; j < 8; j += 4) {
            int c = c0 + tx*8 + j;
            float4 v;
            v.x = acc[i][j+0] + bb[c+0];
            v.y = acc[i][j+1] + bb[c+1];
            v.z = acc[i][j+2] + bb[c+2];
            v.w = acc[i][j+3] + bb[c+3];
            *(float4*)&Cb[r * 256 + c] = v;
        }
    }
}

// ---------------- Kernel 2: per-(b,d) online softmax stats -----------------
__global__ __launch_bounds__(256) void k_stats()
{
    int b  = blockIdx.x >> 3;
    int d0 = (blockIdx.x & 7) << 5;
    int dd = threadIdx.x & 31;
    int g  = threadIdx.x >> 5;     // 0..7
    int d  = d0 + dd;
    const float* base = g_K + b * (NN * DD) + d;

    float m = -1e30f, s = 0.f;
    #pragma unroll 4
    for (int n = g; n < NN; n += 8) {
        float x = base[n * 256];
        float nm = fmaxf(m, x);
        s = fmaf(s, fexp(m - nm), fexp(x - nm));
        m = nm;
    }
    __shared__ float sm[8][32], ss[8][32];
    sm[g][dd] = m; ss[g][dd] = s;
    __syncthreads();
    if (g == 0) {
        float M = sm[0][dd], S = ss[0][dd];
        #pragma unroll
        for (int i = 1; i < 8; i++) {
            float m2 = sm[i][dd], s2 = ss[i][dd];
            float nm = fmaxf(M, m2);
            S = S * fexp(M - nm) + s2 * fexp(m2 - nm);
            M = nm;
        }
        g_colmax[b * 256 + d] = M;
        g_colrcp[b * 256 + d] = 1.0f / S;   // only 2048 divides total
    }
}

// ---------------- Kernel 2b: P = exp(K - max) / sum, in place --------------
__global__ __launch_bounds__(256) void k_norm()
{
    int t = blockIdx.x * 256 + threadIdx.x;       // 4.19M float4 groups
    int i4 = t * 4;
    int d = i4 & 255;
    int b = i4 >> 21;                              // 8192*256 = 2^21
    int cb = b * 256 + d;
    float4 v = *(float4*)&g_K[i4];
    v.x = fexp(v.x - g_colmax[cb+0]) * g_colrcp[cb+0];
    v.y = fexp(v.y - g_colmax[cb+1]) * g_colrcp[cb+1];
    v.z = fexp(v.z - g_colmax[cb+2]) * g_colrcp[cb+2];
    v.w = fexp(v.w - g_colmax[cb+3]) * g_colrcp[cb+3];
    *(float4*)&g_K[i4] = v;
}

// ---------------- Kernel 3: lam partials = P^T @ V (split-K) ---------------
// grid (e_tile=2, d_tile=2, b*32+split)
__global__ __launch_bounds__(256) void k_lam()
{
    __shared__ float As[16][128];   // As[k(n)][d]
    __shared__ float Bs[16][128];   // Bs[k(n)][e]
    int e0 = blockIdx.x * 128;
    int d0 = blockIdx.y * 128;
    int b     = blockIdx.z >> 5;
    int split = blockIdx.z & 31;
    int nbase = b * NN + split * 256;

    int tid = threadIdx.x;
    int tx = tid & 15, ty = tid >> 4;
    float acc[8][8];
    #pragma unroll
    for (int i = 0; i < 8; i++)
        #pragma unroll
        for (int j = 0; j < 8; j++) acc[i][j] = 0.f;

    for (int kk = 0; kk < 256; kk += 16) {
        #pragma unroll
        for (int i = 0; i < 2; i++) {
            int f = tid + i * 256;
            int r = f >> 5, c4 = (f & 31) * 4;
            *(float4*)&As[r][c4] = *(const float4*)&g_K[(nbase + kk + r) * 256 + d0 + c4];
            *(float4*)&Bs[r][c4] = *(const float4*)&g_V[(nbase + kk + r) * 256 + e0 + c4];
        }
        __syncthreads();
        #pragma unroll
        for (int k = 0; k < 16; k++) {
            float a[8], bv[8];
            *(float4*)&a[0]  = *(float4*)&As[k][ty*8];
            *(float4*)&a[4]  = *(float4*)&As[k][ty*8+4];
            *(float4*)&bv[0] = *(float4*)&Bs[k][tx*8];
            *(float4*)&bv[4] = *(float4*)&Bs[k][tx*8+4];
            #pragma unroll
            for (int i = 0; i < 8; i++)
                #pragma unroll
                for (int j = 0; j < 8; j++)
                    acc[i][j] = fmaf(a[i], bv[j], acc[i][j]);
        }
        __syncthreads();
    }
    float* outp = g_lampart + split * (BB*DD*DD);
    #pragma unroll
    for (int i = 0; i < 8; i++) {
        int row = b * 256 + d0 + ty*8 + i;
        #pragma unroll
        for (int j = 0; j < 8; j += 4) {
            int c = e0 + tx*8 + j;
            *(float4*)&outp[row * 256 + c] = *(float4*)&acc[i][j];
        }
    }
}

// ---------------- Kernel 4a: reduce split-K partials -----------------------
__global__ __launch_bounds__(256) void k_red()
{
    int t = blockIdx.x * 256 + threadIdx.x;   // 131072 float4 groups
    float4 a = make_float4(0.f, 0.f, 0.f, 0.f);
    #pragma unroll
    for (int s = 0; s < NSPLIT; s++) {
        float4 v = *(float4*)&g_lampart[s * (BB*DD*DD) + t * 4];
        a.x += v.x; a.y += v.y; a.z += v.z; a.w += v.w;
    }
    *(float4*)&g_lam[t * 4] = a;
}

// ---------------- Kernel 4b: BN stats per d --------------------------------
__global__ __launch_bounds__(256) void k_bnstat(const float* __restrict__ gamma,
                                               const float* __restrict__ beta)
{
    int d = blockIdx.x;
    int tid = threadIdx.x;
    float sum = 0.f, sq = 0.f;
    #pragma unroll
    for (int i = 0; i < 8; i++) {
        int f = tid + i * 256;       // 0..2047
        int b = f >> 8, e = f & 255;
        float v = g_lam[(b * 256 + d) * 256 + e];
        sum += v; sq = fmaf(v, v, sq);
    }
    __shared__ float s1[256], s2[256];
    s1[tid] = sum; s2[tid] = sq;
    __syncthreads();
    for (int st = 128; st > 0; st >>= 1) {
        if (tid < st) { s1[tid] += s1[tid+st]; s2[tid] += s2[tid+st]; }
        __syncthreads();
    }
    if (tid == 0) {
        float mean = s1[0] * (1.0f / 2048.0f);
        float var  = s2[0] * (1.0f / 2048.0f) - mean * mean;
        float rstd = rsqrtf(var + 1e-5f);
        float sc = rstd * gamma[d];
        g_scale[d] = sc;
        g_shift[d] = beta[d] - mean * sc;
    }
}

// ---------------- Kernel 4c: bn = lam*scale + shift ------------------------
__global__ __launch_bounds__(256) void k_bn()
{
    int t = blockIdx.x * 256 + threadIdx.x;
    int i4 = t * 4;
    int d = (i4 >> 8) & 255;
    float sc = g_scale[d], sh = g_shift[d];
    float4 v = *(float4*)&g_lam[i4];
    v.x = fmaf(v.x, sc, sh); v.y = fmaf(v.y, sc, sh);
    v.z = fmaf(v.z, sc, sh); v.w = fmaf(v.w, sc, sh);
    *(float4*)&g_bn[i4] = v;
}

// ---------------- Kernel 5: out = Q[b] @ bn[b] -----------------------------
__global__ __launch_bounds__(256) void k_out(float* __restrict__ out)
{
    __shared__ float As[16][128];
    __shared__ float Bs[16][128];
    int e0 = blockIdx.x * 128;
    int m0 = blockIdx.y * 128;
    int b = m0 >> 13;                 // 8192 rows per batch
    const float* Bbase = g_bn + b * (DD*DD);

    int tid = threadIdx.x;
    int tx = tid & 15, ty = tid >> 4;
    float acc[8][8];
    #pragma unroll
    for (int i = 0; i < 8; i++)
        #pragma unroll
        for (int j = 0; j < 8; j++) acc[i][j] = 0.f;

    for (int kk = 0; kk < 256; kk += 16) {
        #pragma unroll
        for (int i = 0; i < 2; i++) {
            int f = tid + i * 256;
            int r = f >> 2, c4 = (f & 3) * 4;
            float4 v = *(const float4*)&g_Q[(m0 + r) * 256 + kk + c4];
            As[c4+0][r] = v.x; As[c4+1][r] = v.y;
            As[c4+2][r] = v.z; As[c4+3][r] = v.w;
        }
        #pragma unroll
        for (int i = 0; i < 2; i++) {
            int f = tid + i * 256;
            int r = f >> 5, c4 = (f & 31) * 4;
            *(float4*)&Bs[r][c4] = *(const float4*)&Bbase[(kk + r) * 256 + e0 + c4];
        }
        __syncthreads();
        #pragma unroll
        for (int k = 0; k < 16; k++) {
            float a[8], bv[8];
            *(float4*)&a[0]  = *(float4*)&As[k][ty*8];
            *(float4*)&a[4]  = *(float4*)&As[k][ty*8+4];
            *(float4*)&bv[0] = *(float4*)&Bs[k][tx*8];
            *(float4*)&bv[4] = *(float4*)&Bs[k][tx*8+4];
            #pragma unroll
            for (int i = 0; i < 8; i++)
                #pragma unroll
                for (int j = 0; j < 8; j++)
                    acc[i][j] = fmaf(a[i], bv[j], acc[i][j]);
        }
        __syncthreads();
    }
    #pragma unroll
    for (int i = 0; i < 8; i++) {
        int r = m0 + ty*8 + i;
        #pragma unroll
        for (int j = 0; j < 8; j += 4) {
            int c = e0 + tx*8 + j;
            *(float4*)&out[r * 256 + c] = *(float4*)&acc[i][j];
        }
    }
}

// ---------------- launch ---------------------------------------------------
extern "C" void kernel_launch(void* const* d_in, const int* in_sizes, int n_in,
                              void* d_out, int out_size)
{
    const float* feature = (const float*)d_in[0];   // [8,8192,256]
    const float* W_qk    = (const float*)d_in[1];   // [2,256,256]
    const float* b_qk    = (const float*)d_in[2];   // [2,256]
    const float* W_v     = (const float*)d_in[3];   // [256,256]
    const float* b_v     = (const float*)d_in[4];   // [256]
    const float* gamma   = (const float*)d_in[5];   // [256]
    const float* beta    = (const float*)d_in[6];   // [256]
    float* out = (float*)d_out;

    k_qkv<<<dim3(6, 512), 256>>>(feature, W_qk, b_qk, W_v, b_v);
    k_stats<<<64, 256>>>();
    k_norm<<<16384, 256>>>();
    k_lam<<<dim3(2, 2, 256), 256>>>();
    k_red<<<512, 256>>>();
    k_bnstat<<<256, 256>>>(gamma, beta);
    k_bn<<<512, 256>>>();
    k_out<<<dim3(2, 512), 256>>>(out);
}

// round 3
// speedup vs baseline: 1.5972x; 1.5972x over previous
#include <cuda_runtime.h>
#include <cuda_bf16.h>
#include <cstdint>

#define BB 8
#define NN 8192
#define DD 256
#define NSPLIT 32
#define TOTROWS (BB*NN)    // 65536

// ---------------- scratch globals ------------------------------------------
__device__ float g_K[TOTROWS*DD];                 // fp32 K logits
__device__ float g_V[TOTROWS*DD];                 // fp32 V
__device__ __nv_bfloat16 g_Fhi[TOTROWS*DD];
__device__ __nv_bfloat16 g_Flo[TOTROWS*DD];
__device__ __nv_bfloat16 g_Qhi[TOTROWS*DD];
__device__ __nv_bfloat16 g_Qlo[TOTROWS*DD];
__device__ __nv_bfloat16 g_Wthi[768*DD];
__device__ __nv_bfloat16 g_Wtlo[768*DD];
__device__ __nv_bfloat16 g_Pthi[BB*DD*NN];        // P transposed [b][d][n]
__device__ __nv_bfloat16 g_Ptlo[BB*DD*NN];
__device__ __nv_bfloat16 g_Vthi[BB*DD*NN];        // V transposed [b][e][n]
__device__ __nv_bfloat16 g_Vtlo[BB*DD*NN];
__device__ __nv_bfloat16 g_bnThi[BB*DD*DD];       // bn transposed [b][e][d]
__device__ __nv_bfloat16 g_bnTlo[BB*DD*DD];
__device__ float g_colmax[BB*DD];
__device__ float g_colrcp[BB*DD];
__device__ float g_lampart[NSPLIT*BB*DD*DD];
__device__ float g_lam[BB*DD*DD];
__device__ float g_scale[DD];
__device__ float g_shift[DD];

// ---------------- helpers --------------------------------------------------
__device__ __forceinline__ uint32_t smem_to_u32(const void* p) {
    uint32_t a;
    asm("{ .reg .u64 t; cvta.to.shared.u64 t, %1; cvt.u32.u64 %0, t; }" : "=r"(a) : "l"(p));
    return a;
}
#define LDSM4(R, addr) \
    asm volatile("ldmatrix.sync.aligned.m8n8.x4.shared.b16 {%0,%1,%2,%3}, [%4];" \
        : "=r"((R)[0]), "=r"((R)[1]), "=r"((R)[2]), "=r"((R)[3]) : "r"(addr))
#define LDSM2(R, addr) \
    asm volatile("ldmatrix.sync.aligned.m8n8.x2.shared.b16 {%0,%1}, [%2];" \
        : "=r"((R)[0]), "=r"((R)[1]) : "r"(addr))

__device__ __forceinline__ void mma_bf16(float* c, const uint32_t* a, const uint32_t* b) {
    asm volatile("mma.sync.aligned.m16n8k16.row.col.f32.bf16.bf16.f32 "
        "{%0,%1,%2,%3}, {%4,%5,%6,%7}, {%8,%9}, {%0,%1,%2,%3};"
        : "+f"(c[0]), "+f"(c[1]), "+f"(c[2]), "+f"(c[3])
        : "r"(a[0]), "r"(a[1]), "r"(a[2]), "r"(a[3]), "r"(b[0]), "r"(b[1]));
}

__device__ __forceinline__ float fexp(float x) {
    float y = x * 1.4426950408889634f;
    y = fmaxf(y, -126.0f);
    float r = rintf(y);
    float t = (y - r) * 0.6931471805599453f;
    float p = 1.3888889e-3f;
    p = fmaf(p, t, 8.3333333e-3f);
    p = fmaf(p, t, 4.1666667e-2f);
    p = fmaf(p, t, 1.6666667e-1f);
    p = fmaf(p, t, 0.5f);
    p = fmaf(p, t, 1.0f);
    p = fmaf(p, t, 1.0f);
    float sc = __int_as_float(((int)r + 127) << 23);
    return p * sc;
}
__device__ __forceinline__ void split2(float v, __nv_bfloat16& h, __nv_bfloat16& l) {
    h = __float2bfloat16(v);
    l = __float2bfloat16(v - __bfloat162float(h));
}

// ---------------- feature split --------------------------------------------
__global__ __launch_bounds__(256) void k_split(const float* __restrict__ X)
{
    int t = blockIdx.x * 256 + threadIdx.x;
    float4 v = *(const float4*)&X[t * 4];
    __nv_bfloat16 h[4], l[4];
    split2(v.x, h[0], l[0]); split2(v.y, h[1], l[1]);
    split2(v.z, h[2], l[2]); split2(v.w, h[3], l[3]);
    *(uint2*)&g_Fhi[t * 4] = *(uint2*)h;
    *(uint2*)&g_Flo[t * 4] = *(uint2*)l;
}

// ---------------- W transpose + split --------------------------------------
__global__ __launch_bounds__(256) void k_wsplit(const float* __restrict__ Wqk,
                                               const float* __restrict__ Wv)
{
    int n = blockIdx.x;        // 0..767
    int k = threadIdx.x;       // 0..255
    int sec = n >> 8, nn = n & 255;
    float w = (sec == 0) ? Wqk[k * 256 + nn]
            : (sec == 1) ? Wqk[65536 + k * 256 + nn]
                         : Wv[k * 256 + nn];
    __nv_bfloat16 h, l; split2(w, h, l);
    g_Wthi[n * 256 + k] = h;
    g_Wtlo[n * 256 + k] = l;
}

// ---------------- shared MMA GEMM kernel ------------------------------------
// mode 0: C[65536x768] = F @ Wt^T  -> scatter Q(split)/K/V (+bias)
// mode 1: C[65536x256] = Q @ bnT^T -> fp32 out
// mode 2: lam partials: C[256x256] = Pt @ Vt^T over 256-seq split
// Block tile 128x128, 8 warps each 64x32 (2x4 warp grid), K-chunk 32.
#define ROWB 80                  // padded smem row bytes (32 bf16 + 8 pad)
#define BUFB (128*ROWB)          // 10240 bytes per operand buffer

__global__ __launch_bounds__(256) void k_mma(int mode, const float* __restrict__ bqk,
                                             const float* __restrict__ bv,
                                             float* __restrict__ outp)
{
    __shared__ __align__(16) unsigned char sm[4*BUFB];
    int tid = threadIdx.x, lane = tid & 31, wid = tid >> 5;
    int wm = wid >> 2, wn = wid & 3;

    const __nv_bfloat16 *Ah, *Al, *Bh, *Bl;
    long astr, bstr;
    int m0, ncol0;
    if (mode == 0) {
        ncol0 = blockIdx.x * 128; m0 = blockIdx.y * 128;
        Ah = g_Fhi + (long)m0 * 256;  Al = g_Flo + (long)m0 * 256;
        Bh = g_Wthi + (long)ncol0 * 256; Bl = g_Wtlo + (long)ncol0 * 256;
        astr = bstr = 256;
    } else if (mode == 1) {
        ncol0 = blockIdx.x * 128; m0 = blockIdx.y * 128;
        int b = m0 >> 13;
        Ah = g_Qhi + (long)m0 * 256;  Al = g_Qlo + (long)m0 * 256;
        Bh = g_bnThi + (long)b * 65536 + (long)ncol0 * 256;
        Bl = g_bnTlo + (long)b * 65536 + (long)ncol0 * 256;
        astr = bstr = 256;
    } else {
        int e0 = blockIdx.x * 128, d0 = blockIdx.y * 128;
        int b = blockIdx.z >> 5, sp = blockIdx.z & 31;
        long ab = (long)(b * 256 + d0) * NN + sp * 256;
        long bb = (long)(b * 256 + e0) * NN + sp * 256;
        Ah = g_Pthi + ab; Al = g_Ptlo + ab;
        Bh = g_Vthi + bb; Bl = g_Vtlo + bb;
        astr = bstr = NN;
        m0 = d0; ncol0 = e0;
    }

    float c[16][4];
    #pragma unroll
    for (int i = 0; i < 16; i++)
        #pragma unroll
        for (int j = 0; j < 4; j++) c[i][j] = 0.f;

    uint32_t smb = smem_to_u32(sm);

    for (int ch = 0; ch < 8; ch++) {
        int kk = ch * 32;
        #pragma unroll
        for (int buf = 0; buf < 4; buf++) {
            const __nv_bfloat16* src = (buf == 0) ? Ah : (buf == 1) ? Al
                                     : (buf == 2) ? Bh : Bl;
            long str = (buf < 2) ? astr : bstr;
            #pragma unroll
            for (int j = 0; j < 2; j++) {
                int idx = tid + j * 256;
                int row = idx >> 2, cc = idx & 3;
                *(uint4*)(sm + buf * BUFB + row * ROWB + cc * 16) =
                    *(const uint4*)(src + (long)row * str + kk + cc * 8);
            }
        }
        __syncthreads();
        #pragma unroll
        for (int k0 = 0; k0 < 2; k0++) {
            uint32_t a_h[4][4], a_l[4][4], b_h[4][2], b_l[4][2];
            #pragma unroll
            for (int mt = 0; mt < 4; mt++) {
                uint32_t ra = smb + (wm*64 + mt*16 + (lane & 15)) * ROWB
                            + (k0*16 + (lane >> 4) * 8) * 2;
                LDSM4(a_h[mt], ra);
                LDSM4(a_l[mt], ra + BUFB);
            }
            #pragma unroll
            for (int nt = 0; nt < 4; nt++) {
                uint32_t rb = smb + 2*BUFB + (wn*32 + nt*8 + (lane & 7)) * ROWB
                            + (k0*16 + ((lane >> 3) & 1) * 8) * 2;
                LDSM2(b_h[nt], rb);
                LDSM2(b_l[nt], rb + BUFB);
            }
            #pragma unroll
            for (int mt = 0; mt < 4; mt++)
                #pragma unroll
                for (int nt = 0; nt < 4; nt++) {
                    mma_bf16(c[mt*4+nt], a_h[mt], b_h[nt]);
                    mma_bf16(c[mt*4+nt], a_h[mt], b_l[nt]);
                    mma_bf16(c[mt*4+nt], a_l[mt], b_h[nt]);
                }
        }
        __syncthreads();
    }

    // epilogue
    int rbase = m0 + wm * 64;
    int cl0 = wn * 32;
    #pragma unroll
    for (int mt = 0; mt < 4; mt++) {
        #pragma unroll
        for (int nt = 0; nt < 4; nt++) {
            float* cc = c[mt*4+nt];
            int r0 = rbase + mt*16 + (lane >> 2);
            int cl = cl0 + nt*8 + (lane & 3)*2;
            if (mode == 1) {
                float2 v0 = {cc[0], cc[1]}, v1 = {cc[2], cc[3]};
                *(float2*)&outp[(long)r0 * 256 + ncol0 + cl] = v0;
                *(float2*)&outp[(long)(r0+8) * 256 + ncol0 + cl] = v1;
            } else if (mode == 2) {
                int b = blockIdx.z >> 5, sp = blockIdx.z & 31;
                float* op = g_lampart + (long)sp * (BB*DD*DD) + (long)b * 65536;
                float2 v0 = {cc[0], cc[1]}, v1 = {cc[2], cc[3]};
                *(float2*)&op[(long)r0 * 256 + ncol0 + cl] = v0;
                *(float2*)&op[(long)(r0+8) * 256 + ncol0 + cl] = v1;
            } else {
                int sec = ncol0 >> 8;
                int cg = (ncol0 & 255) + cl;
                if (sec == 0) {
                    float b0 = bqk[cg], b1 = bqk[cg+1];
                    #pragma unroll
                    for (int hrow = 0; hrow < 2; hrow++) {
                        int r = r0 + hrow * 8;
                        float v0 = cc[hrow*2+0] + b0, v1 = cc[hrow*2+1] + b1;
                        __nv_bfloat16 h0,l0,h1,l1;
                        split2(v0,h0,l0); split2(v1,h1,l1);
                        __nv_bfloat162 ph; ph.x = h0; ph.y = h1;
                        __nv_bfloat162 pl; pl.x = l0; pl.y = l1;
                        *(__nv_bfloat162*)&g_Qhi[(long)r*256 + cg] = ph;
                        *(__nv_bfloat162*)&g_Qlo[(long)r*256 + cg] = pl;
                    }
                } else {
                    const float* bb = (sec == 1) ? bqk + 256 : bv;
                    float* dst = (sec == 1) ? g_K : g_V;
                    float b0 = bb[cg], b1 = bb[cg+1];
                    float2 v0 = {cc[0] + b0, cc[1] + b1};
                    float2 v1 = {cc[2] + b0, cc[3] + b1};
                    *(float2*)&dst[(long)r0 * 256 + cg] = v0;
                    *(float2*)&dst[(long)(r0+8) * 256 + cg] = v1;
                }
            }
        }
    }
}

// ---------------- softmax stats (reads fp32 K) -----------------------------
__global__ __launch_bounds__(256) void k_stats()
{
    int b  = blockIdx.x >> 3;
    int d0 = (blockIdx.x & 7) << 5;
    int dd = threadIdx.x & 31;
    int g  = threadIdx.x >> 5;
    int d  = d0 + dd;
    const float* base = g_K + b * (NN * DD) + d;

    float m = -1e30f, s = 0.f;
    #pragma unroll 4
    for (int n = g; n < NN; n += 8) {
        float x = base[n * 256];
        float nm = fmaxf(m, x);
        s = fmaf(s, fexp(m - nm), fexp(x - nm));
        m = nm;
    }
    __shared__ float sm[8][32], ss[8][32];
    sm[g][dd] = m; ss[g][dd] = s;
    __syncthreads();
    if (g == 0) {
        float M = sm[0][dd], S = ss[0][dd];
        #pragma unroll
        for (int i = 1; i < 8; i++) {
            float m2 = sm[i][dd], s2 = ss[i][dd];
            float nm = fmaxf(M, m2);
            S = S * fexp(M - nm) + s2 * fexp(m2 - nm);
            M = nm;
        }
        g_colmax[b * 256 + d] = M;
        g_colrcp[b * 256 + d] = 1.0f / S;
    }
}

// ---------------- P transpose: exp-normalize + split -> Pt[b][d][n] --------
__global__ void k_normT()
{
    __shared__ float tile[32][33];
    int b = blockIdx.z, d0 = blockIdx.y * 32, n0 = blockIdx.x * 32;
    int tx = threadIdx.x, ty = threadIdx.y;   // 32 x 8
    float mx = g_colmax[b * 256 + d0 + tx];
    float rc = g_colrcp[b * 256 + d0 + tx];
    #pragma unroll
    for (int i = 0; i < 4; i++) {
        int n = n0 + ty + i * 8;
        float kv = g_K[((long)b * NN + n) * 256 + d0 + tx];
        tile[ty + i * 8][tx] = fexp(kv - mx) * rc;    // tile[n][d]
    }
    __syncthreads();
    #pragma unroll
    for (int i = 0; i < 4; i++) {
        int d = d0 + ty + i * 8;
        float v = tile[tx][ty + i * 8];
        __nv_bfloat16 h, l; split2(v, h, l);
        long o = (long)(b * 256 + d) * NN + n0 + tx;
        g_Pthi[o] = h; g_Ptlo[o] = l;
    }
}

// ---------------- V transpose + split -> Vt[b][e][n] -----------------------
__global__ void k_vT()
{
    __shared__ float tile[32][33];
    int b = blockIdx.z, e0 = blockIdx.y * 32, n0 = blockIdx.x * 32;
    int tx = threadIdx.x, ty = threadIdx.y;
    #pragma unroll
    for (int i = 0; i < 4; i++) {
        int n = n0 + ty + i * 8;
        tile[ty + i * 8][tx] = g_V[((long)b * NN + n) * 256 + e0 + tx];
    }
    __syncthreads();
    #pragma unroll
    for (int i = 0; i < 4; i++) {
        int e = e0 + ty + i * 8;
        float v = tile[tx][ty + i * 8];
        __nv_bfloat16 h, l; split2(v, h, l);
        long o = (long)(b * 256 + e) * NN + n0 + tx;
        g_Vthi[o] = h; g_Vtlo[o] = l;
    }
}

// ---------------- reduce split-K -------------------------------------------
__global__ __launch_bounds__(256) void k_red()
{
    int t = blockIdx.x * 256 + threadIdx.x;
    float4 a = make_float4(0.f, 0.f, 0.f, 0.f);
    #pragma unroll
    for (int s = 0; s < NSPLIT; s++) {
        float4 v = *(float4*)&g_lampart[(long)s * (BB*DD*DD) + t * 4];
        a.x += v.x; a.y += v.y; a.z += v.z; a.w += v.w;
    }
    *(float4*)&g_lam[t * 4] = a;
}

// ---------------- BN stats per d -------------------------------------------
__global__ __launch_bounds__(256) void k_bnstat(const float* __restrict__ gamma,
                                               const float* __restrict__ beta)
{
    int d = blockIdx.x;
    int tid = threadIdx.x;
    float sum = 0.f, sq = 0.f;
    #pragma unroll
    for (int i = 0; i < 8; i++) {
        int f = tid + i * 256;
        int b = f >> 8, e = f & 255;
        float v = g_lam[(b * 256 + d) * 256 + e];
        sum += v; sq = fmaf(v, v, sq);
    }
    __shared__ float s1[256], s2[256];
    s1[tid] = sum; s2[tid] = sq;
    __syncthreads();
    for (int st = 128; st > 0; st >>= 1) {
        if (tid < st) { s1[tid] += s1[tid+st]; s2[tid] += s2[tid+st]; }
        __syncthreads();
    }
    if (tid == 0) {
        float mean = s1[0] * (1.0f / 2048.0f);
        float var  = s2[0] * (1.0f / 2048.0f) - mean * mean;
        float rstd = rsqrtf(var + 1e-5f);
        float sc = rstd * gamma[d];
        g_scale[d] = sc;
        g_shift[d] = beta[d] - mean * sc;
    }
}

// ---------------- bnT = transpose(BN(lam)), split --------------------------
__global__ void k_bnT()
{
    __shared__ float tile[32][33];
    int b = blockIdx.z, dt = blockIdx.y * 32, et = blockIdx.x * 32;
    int tx = threadIdx.x, ty = threadIdx.y;
    #pragma unroll
    for (int i = 0; i < 4; i++) {
        int d = dt + ty + i * 8;
        float sc = g_scale[d], sh = g_shift[d];
        tile[ty + i * 8][tx] = fmaf(g_lam[(b * 256 + d) * 256 + et + tx], sc, sh);
    }
    __syncthreads();
    #pragma unroll
    for (int i = 0; i < 4; i++) {
        int e = et + ty + i * 8;
        float v = tile[tx][ty + i * 8];
        int o = (b * 256 + e) * 256 + dt + tx;
        __nv_bfloat16 h, l; split2(v, h, l);
        g_bnThi[o] = h; g_bnTlo[o] = l;
    }
}

// ---------------- launch ---------------------------------------------------
extern "C" void kernel_launch(void* const* d_in, const int* in_sizes, int n_in,
                              void* d_out, int out_size)
{
    const float* feature = (const float*)d_in[0];
    const float* W_qk    = (const float*)d_in[1];
    const float* b_qk    = (const float*)d_in[2];
    const float* W_v     = (const float*)d_in[3];
    const float* b_v     = (const float*)d_in[4];
    const float* gamma   = (const float*)d_in[5];
    const float* beta    = (const float*)d_in[6];
    float* out = (float*)d_out;

    k_split<<<16384, 256>>>(feature);
    k_wsplit<<<768, 256>>>(W_qk, W_v);
    k_mma<<<dim3(6, 512), 256>>>(0, b_qk, b_v, nullptr);      // QKV
    k_stats<<<64, 256>>>();
    k_normT<<<dim3(256, 8, 8), dim3(32, 8)>>>();
    k_vT<<<dim3(256, 8, 8), dim3(32, 8)>>>();
    k_mma<<<dim3(2, 2, 256), 256>>>(2, nullptr, nullptr, nullptr);  // lam partials
    k_red<<<512, 256>>>();
    k_bnstat<<<256, 256>>>(gamma, beta);
    k_bnT<<<dim3(8, 8, 8), dim3(32, 8)>>>();
    k_mma<<<dim3(2, 512), 256>>>(1, nullptr, nullptr, out);   // out
}

// round 5
// speedup vs baseline: 1.9628x; 1.2289x over previous
#include <cuda_runtime.h>
#include <cuda_bf16.h>
#include <cstdint>

#define BB 8
#define NN 8192
#define DD 256
#define NSPLIT 16
#define NCHUNK 32          // k_stats row chunks (8192/256)
#define TOTROWS (BB*NN)    // 65536

// ---------------- scratch globals ------------------------------------------
__device__ float g_K[TOTROWS*DD];                 // fp32 K logits
__device__ float g_V[TOTROWS*DD];                 // fp32 V
__device__ __nv_bfloat16 g_Fhi[TOTROWS*DD];
__device__ __nv_bfloat16 g_Flo[TOTROWS*DD];
__device__ __nv_bfloat16 g_Qhi[TOTROWS*DD];
__device__ __nv_bfloat16 g_Qlo[TOTROWS*DD];
__device__ __nv_bfloat16 g_Wthi[768*DD];
__device__ __nv_bfloat16 g_Wtlo[768*DD];
__device__ __nv_bfloat16 g_Pthi[BB*DD*NN];        // P transposed [b][d][n]
__device__ __nv_bfloat16 g_Ptlo[BB*DD*NN];
__device__ __nv_bfloat16 g_Vthi[BB*DD*NN];        // V transposed [b][e][n]
__device__ __nv_bfloat16 g_Vtlo[BB*DD*NN];
__device__ __nv_bfloat16 g_bnThi[BB*DD*DD];       // bn transposed [b][e][d]
__device__ __nv_bfloat16 g_bnTlo[BB*DD*DD];
__device__ float g_pmax[NCHUNK*BB*DD];
__device__ float g_psum[NCHUNK*BB*DD];
__device__ float g_colmax[BB*DD];
__device__ float g_colrcp[BB*DD];
__device__ float g_lampart[NSPLIT*BB*DD*DD];
__device__ float g_lam[BB*DD*DD];
__device__ float g_scale[DD];
__device__ float g_shift[DD];

// ---------------- helpers --------------------------------------------------
__device__ __forceinline__ uint32_t smem_to_u32(const void* p) {
    uint32_t a;
    asm("{ .reg .u64 t; cvta.to.shared.u64 t, %1; cvt.u32.u64 %0, t; }" : "=r"(a) : "l"(p));
    return a;
}
#define LDSM4(R, addr) \
    asm volatile("ldmatrix.sync.aligned.m8n8.x4.shared.b16 {%0,%1,%2,%3}, [%4];" \
        : "=r"((R)[0]), "=r"((R)[1]), "=r"((R)[2]), "=r"((R)[3]) : "r"(addr))
#define LDSM2(R, addr) \
    asm volatile("ldmatrix.sync.aligned.m8n8.x2.shared.b16 {%0,%1}, [%2];" \
        : "=r"((R)[0]), "=r"((R)[1]) : "r"(addr))

__device__ __forceinline__ void mma_bf16(float* c, const uint32_t* a, const uint32_t* b) {
    asm volatile("mma.sync.aligned.m16n8k16.row.col.f32.bf16.bf16.f32 "
        "{%0,%1,%2,%3}, {%4,%5,%6,%7}, {%8,%9}, {%0,%1,%2,%3};"
        : "+f"(c[0]), "+f"(c[1]), "+f"(c[2]), "+f"(c[3])
        : "r"(a[0]), "r"(a[1]), "r"(a[2]), "r"(a[3]), "r"(b[0]), "r"(b[1]));
}

__device__ __forceinline__ float fexp(float x) {
    float y = x * 1.4426950408889634f;
    y = fmaxf(y, -126.0f);
    float r = rintf(y);
    float t = (y - r) * 0.6931471805599453f;
    float p = 1.3888889e-3f;
    p = fmaf(p, t, 8.3333333e-3f);
    p = fmaf(p, t, 4.1666667e-2f);
    p = fmaf(p, t, 1.6666667e-1f);
    p = fmaf(p, t, 0.5f);
    p = fmaf(p, t, 1.0f);
    p = fmaf(p, t, 1.0f);
    float sc = __int_as_float(((int)r + 127) << 23);
    return p * sc;
}
__device__ __forceinline__ void split2(float v, __nv_bfloat16& h, __nv_bfloat16& l) {
    h = __float2bfloat16(v);
    l = __float2bfloat16(v - __bfloat162float(h));
}

// ---------------- feature split --------------------------------------------
__global__ __launch_bounds__(256) void k_split(const float* __restrict__ X)
{
    int t = blockIdx.x * 256 + threadIdx.x;
    float4 v = *(const float4*)&X[t * 4];
    __nv_bfloat16 h[4], l[4];
    split2(v.x, h[0], l[0]); split2(v.y, h[1], l[1]);
    split2(v.z, h[2], l[2]); split2(v.w, h[3], l[3]);
    *(uint2*)&g_Fhi[t * 4] = *(uint2*)h;
    *(uint2*)&g_Flo[t * 4] = *(uint2*)l;
}

// ---------------- W transpose + split --------------------------------------
__global__ __launch_bounds__(256) void k_wsplit(const float* __restrict__ Wqk,
                                               const float* __restrict__ Wv)
{
    int n = blockIdx.x;
    int k = threadIdx.x;
    int sec = n >> 8, nn = n & 255;
    float w = (sec == 0) ? Wqk[k * 256 + nn]
            : (sec == 1) ? Wqk[65536 + k * 256 + nn]
                         : Wv[k * 256 + nn];
    __nv_bfloat16 h, l; split2(w, h, l);
    g_Wthi[n * 256 + k] = h;
    g_Wtlo[n * 256 + k] = l;
}

// ---------------- shared MMA GEMM kernel ------------------------------------
// mode 0: C[65536x768] = F @ Wt^T  -> scatter Q(split)/K/V (+bias)
// mode 1: C[65536x256] = Q @ bnT^T -> fp32 out
// mode 2: lam partials: C[256x256] = Pt @ Vt^T over 512-seq split
#define ROWB 80
#define BUFB (128*ROWB)

__global__ __launch_bounds__(256) void k_mma(int mode, const float* __restrict__ bqk,
                                             const float* __restrict__ bv,
                                             float* __restrict__ outp)
{
    __shared__ __align__(16) unsigned char sm[4*BUFB];
    int tid = threadIdx.x, lane = tid & 31, wid = tid >> 5;
    int wm = wid >> 2, wn = wid & 3;

    const __nv_bfloat16 *Ah, *Al, *Bh, *Bl;
    long astr, bstr;
    int m0, ncol0;
    int nk = (mode == 2) ? 16 : 8;
    if (mode == 0) {
        ncol0 = blockIdx.x * 128; m0 = blockIdx.y * 128;
        Ah = g_Fhi + (long)m0 * 256;  Al = g_Flo + (long)m0 * 256;
        Bh = g_Wthi + (long)ncol0 * 256; Bl = g_Wtlo + (long)ncol0 * 256;
        astr = bstr = 256;
    } else if (mode == 1) {
        ncol0 = blockIdx.x * 128; m0 = blockIdx.y * 128;
        int b = m0 >> 13;
        Ah = g_Qhi + (long)m0 * 256;  Al = g_Qlo + (long)m0 * 256;
        Bh = g_bnThi + (long)b * 65536 + (long)ncol0 * 256;
        Bl = g_bnTlo + (long)b * 65536 + (long)ncol0 * 256;
        astr = bstr = 256;
    } else {
        int e0 = blockIdx.x * 128, d0 = blockIdx.y * 128;
        int b = blockIdx.z >> 4, sp = blockIdx.z & 15;
        long ab = (long)(b * 256 + d0) * NN + sp * 512;
        long bb = (long)(b * 256 + e0) * NN + sp * 512;
        Ah = g_Pthi + ab; Al = g_Ptlo + ab;
        Bh = g_Vthi + bb; Bl = g_Vtlo + bb;
        astr = bstr = NN;
        m0 = d0; ncol0 = e0;
    }

    float c[16][4];
    #pragma unroll
    for (int i = 0; i < 16; i++)
        #pragma unroll
        for (int j = 0; j < 4; j++) c[i][j] = 0.f;

    uint32_t smb = smem_to_u32(sm);

    for (int ch = 0; ch < nk; ch++) {
        int kk = ch * 32;
        #pragma unroll
        for (int buf = 0; buf < 4; buf++) {
            const __nv_bfloat16* src = (buf == 0) ? Ah : (buf == 1) ? Al
                                     : (buf == 2) ? Bh : Bl;
            long str = (buf < 2) ? astr : bstr;
            #pragma unroll
            for (int j = 0; j < 2; j++) {
                int idx = tid + j * 256;
                int row = idx >> 2, cc = idx & 3;
                *(uint4*)(sm + buf * BUFB + row * ROWB + cc * 16) =
                    *(const uint4*)(src + (long)row * str + kk + cc * 8);
            }
        }
        __syncthreads();
        #pragma unroll
        for (int k0 = 0; k0 < 2; k0++) {
            uint32_t a_h[4][4], a_l[4][4], b_h[4][2], b_l[4][2];
            #pragma unroll
            for (int mt = 0; mt < 4; mt++) {
                uint32_t ra = smb + (wm*64 + mt*16 + (lane & 15)) * ROWB
                            + (k0*16 + (lane >> 4) * 8) * 2;
                LDSM4(a_h[mt], ra);
                LDSM4(a_l[mt], ra + BUFB);
            }
            #pragma unroll
            for (int nt = 0; nt < 4; nt++) {
                uint32_t rb = smb + 2*BUFB + (wn*32 + nt*8 + (lane & 7)) * ROWB
                            + (k0*16 + ((lane >> 3) & 1) * 8) * 2;
                LDSM2(b_h[nt], rb);
                LDSM2(b_l[nt], rb + BUFB);
            }
            #pragma unroll
            for (int mt = 0; mt < 4; mt++)
                #pragma unroll
                for (int nt = 0; nt < 4; nt++) {
                    mma_bf16(c[mt*4+nt], a_h[mt], b_h[nt]);
                    mma_bf16(c[mt*4+nt], a_h[mt], b_l[nt]);
                    mma_bf16(c[mt*4+nt], a_l[mt], b_h[nt]);
                }
        }
        __syncthreads();
    }

    // epilogue
    int rbase = m0 + wm * 64;
    int cl0 = wn * 32;
    #pragma unroll
    for (int mt = 0; mt < 4; mt++) {
        #pragma unroll
        for (int nt = 0; nt < 4; nt++) {
            float* cc = c[mt*4+nt];
            int r0 = rbase + mt*16 + (lane >> 2);
            int cl = cl0 + nt*8 + (lane & 3)*2;
            if (mode == 1) {
                float2 v0 = {cc[0], cc[1]}, v1 = {cc[2], cc[3]};
                *(float2*)&outp[(long)r0 * 256 + ncol0 + cl] = v0;
                *(float2*)&outp[(long)(r0+8) * 256 + ncol0 + cl] = v1;
            } else if (mode == 2) {
                int b = blockIdx.z >> 4, sp = blockIdx.z & 15;
                float* op = g_lampart + (long)sp * (BB*DD*DD) + (long)b * 65536;
                float2 v0 = {cc[0], cc[1]}, v1 = {cc[2], cc[3]};
                *(float2*)&op[(long)r0 * 256 + ncol0 + cl] = v0;
                *(float2*)&op[(long)(r0+8) * 256 + ncol0 + cl] = v1;
            } else {
                int sec = ncol0 >> 8;
                int cg = (ncol0 & 255) + cl;
                if (sec == 0) {
                    float b0 = bqk[cg], b1 = bqk[cg+1];
                    #pragma unroll
                    for (int hrow = 0; hrow < 2; hrow++) {
                        int r = r0 + hrow * 8;
                        float v0 = cc[hrow*2+0] + b0, v1 = cc[hrow*2+1] + b1;
                        __nv_bfloat16 h0,l0,h1,l1;
                        split2(v0,h0,l0); split2(v1,h1,l1);
                        __nv_bfloat162 ph; ph.x = h0; ph.y = h1;
                        __nv_bfloat162 pl; pl.x = l0; pl.y = l1;
                        *(__nv_bfloat162*)&g_Qhi[(long)r*256 + cg] = ph;
                        *(__nv_bfloat162*)&g_Qlo[(long)r*256 + cg] = pl;
                    }
                } else {
                    const float* bb = (sec == 1) ? bqk + 256 : bv;
                    float* dst = (sec == 1) ? g_K : g_V;
                    float b0 = bb[cg], b1 = bb[cg+1];
                    float2 v0 = {cc[0] + b0, cc[1] + b1};
                    float2 v1 = {cc[2] + b0, cc[3] + b1};
                    *(float2*)&dst[(long)r0 * 256 + cg] = v0;
                    *(float2*)&dst[(long)(r0+8) * 256 + cg] = v1;
                }
            }
        }
    }
}

// ---------------- softmax stats phase A: per-chunk partials ----------------
// grid (NCHUNK, 64): each block = 256-row chunk of one (b, 32-d tile)
__global__ __launch_bounds__(256) void k_stats1()
{
    int ch = blockIdx.x;
    int b  = blockIdx.y >> 3;
    int d0 = (blockIdx.y & 7) << 5;
    int dd = threadIdx.x & 31;
    int g  = threadIdx.x >> 5;
    int d  = d0 + dd;
    const float* base = g_K + ((long)b * NN + ch * 256) * 256 + d;

    float m = -1e30f, s = 0.f;
    #pragma unroll 4
    for (int n = g; n < 256; n += 8) {
        float x = base[(long)n * 256];
        float nm = fmaxf(m, x);
        s = fmaf(s, fexp(m - nm), fexp(x - nm));
        m = nm;
    }
    __shared__ float sm[8][32], ss[8][32];
    sm[g][dd] = m; ss[g][dd] = s;
    __syncthreads();
    if (g == 0) {
        float M = sm[0][dd], S = ss[0][dd];
        #pragma unroll
        for (int i = 1; i < 8; i++) {
            float m2 = sm[i][dd], s2 = ss[i][dd];
            float nm = fmaxf(M, m2);
            S = S * fexp(M - nm) + s2 * fexp(m2 - nm);
            M = nm;
        }
        g_pmax[ch * (BB*DD) + b * 256 + d] = M;
        g_psum[ch * (BB*DD) + b * 256 + d] = S;
    }
}

// ---------------- phase B: combine chunk partials --------------------------
__global__ __launch_bounds__(256) void k_stats2()
{
    int t = blockIdx.x * 256 + threadIdx.x;   // 0..2047 over (b,d)
    if (t >= BB*DD) return;
    float M = g_pmax[t], S = g_psum[t];
    #pragma unroll
    for (int i = 1; i < NCHUNK; i++) {
        float m2 = g_pmax[i * (BB*DD) + t], s2 = g_psum[i * (BB*DD) + t];
        float nm = fmaxf(M, m2);
        S = S * fexp(M - nm) + s2 * fexp(m2 - nm);
        M = nm;
    }
    g_colmax[t] = M;
    g_colrcp[t] = 1.0f / S;
}

// ---------------- P transpose: exp-normalize + split -> Pt[b][d][n] --------
// 64(n) x 32(d) tiles; stores are 128B per warp per array
__global__ __launch_bounds__(256) void k_normT()
{
    __shared__ float tile[64][33];
    int b = blockIdx.z, d0 = blockIdx.y * 32, n0 = blockIdx.x * 64;
    int lx = threadIdx.x & 31, ly = threadIdx.x >> 5;      // load: lx=d, ly=n-group
    float mx = g_colmax[b * 256 + d0 + lx];
    float rc = g_colrcp[b * 256 + d0 + lx];
    #pragma unroll
    for (int i = 0; i < 8; i++) {
        int n = ly + i * 8;
        float kv = g_K[((long)b * NN + n0 + n) * 256 + d0 + lx];
        tile[n][lx] = fexp(kv - mx) * rc;
    }
    __syncthreads();
    int sx = threadIdx.x & 63, sy = threadIdx.x >> 6;      // store: sx=n, sy=d-group
    #pragma unroll
    for (int j = 0; j < 8; j++) {
        int dl = sy + j * 4;
        float v = tile[sx][dl];
        __nv_bfloat16 h, l; split2(v, h, l);
        long o = (long)(b * 256 + d0 + dl) * NN + n0 + sx;
        g_Pthi[o] = h; g_Ptlo[o] = l;
    }
}

// ---------------- V transpose + split -> Vt[b][e][n] -----------------------
__global__ __launch_bounds__(256) void k_vT()
{
    __shared__ float tile[64][33];
    int b = blockIdx.z, e0 = blockIdx.y * 32, n0 = blockIdx.x * 64;
    int lx = threadIdx.x & 31, ly = threadIdx.x >> 5;
    #pragma unroll
    for (int i = 0; i < 8; i++) {
        int n = ly + i * 8;
        tile[n][lx] = g_V[((long)b * NN + n0 + n) * 256 + e0 + lx];
    }
    __syncthreads();
    int sx = threadIdx.x & 63, sy = threadIdx.x >> 6;
    #pragma unroll
    for (int j = 0; j < 8; j++) {
        int el = sy + j * 4;
        float v = tile[sx][el];
        __nv_bfloat16 h, l; split2(v, h, l);
        long o = (long)(b * 256 + e0 + el) * NN + n0 + sx;
        g_Vthi[o] = h; g_Vtlo[o] = l;
    }
}

// ---------------- reduce split-K -------------------------------------------
__global__ __launch_bounds__(256) void k_red()
{
    int t = blockIdx.x * 256 + threadIdx.x;
    float4 a = make_float4(0.f, 0.f, 0.f, 0.f);
    #pragma unroll
    for (int s = 0; s < NSPLIT; s++) {
        float4 v = *(float4*)&g_lampart[(long)s * (BB*DD*DD) + t * 4];
        a.x += v.x; a.y += v.y; a.z += v.z; a.w += v.w;
    }
    *(float4*)&g_lam[t * 4] = a;
}

// ---------------- BN stats per d -------------------------------------------
__global__ __launch_bounds__(256) void k_bnstat(const float* __restrict__ gamma,
                                               const float* __restrict__ beta)
{
    int d = blockIdx.x;
    int tid = threadIdx.x;
    float sum = 0.f, sq = 0.f;
    #pragma unroll
    for (int i = 0; i < 8; i++) {
        int f = tid + i * 256;
        int b = f >> 8, e = f & 255;
        float v = g_lam[(b * 256 + d) * 256 + e];
        sum += v; sq = fmaf(v, v, sq);
    }
    __shared__ float s1[256], s2[256];
    s1[tid] = sum; s2[tid] = sq;
    __syncthreads();
    for (int st = 128; st > 0; st >>= 1) {
        if (tid < st) { s1[tid] += s1[tid+st]; s2[tid] += s2[tid+st]; }
        __syncthreads();
    }
    if (tid == 0) {
        float mean = s1[0] * (1.0f / 2048.0f);
        float var  = s2[0] * (1.0f / 2048.0f) - mean * mean;
        float rstd = rsqrtf(var + 1e-5f);
        float sc = rstd * gamma[d];
        g_scale[d] = sc;
        g_shift[d] = beta[d] - mean * sc;
    }
}

// ---------------- bnT = transpose(BN(lam)), split --------------------------
__global__ void k_bnT()
{
    __shared__ float tile[32][33];
    int b = blockIdx.z, dt = blockIdx.y * 32, et = blockIdx.x * 32;
    int tx = threadIdx.x, ty = threadIdx.y;
    #pragma unroll
    for (int i = 0; i < 4; i++) {
        int d = dt + ty + i * 8;
        float sc = g_scale[d], sh = g_shift[d];
        tile[ty + i * 8][tx] = fmaf(g_lam[(b * 256 + d) * 256 + et + tx], sc, sh);
    }
    __syncthreads();
    #pragma unroll
    for (int i = 0; i < 4; i++) {
        int e = et + ty + i * 8;
        float v = tile[tx][ty + i * 8];
        int o = (b * 256 + e) * 256 + dt + tx;
        __nv_bfloat16 h, l; split2(v, h, l);
        g_bnThi[o] = h; g_bnTlo[o] = l;
    }
}

// ---------------- launch ---------------------------------------------------
extern "C" void kernel_launch(void* const* d_in, const int* in_sizes, int n_in,
                              void* d_out, int out_size)
{
    const float* feature = (const float*)d_in[0];
    const float* W_qk    = (const float*)d_in[1];
    const float* b_qk    = (const float*)d_in[2];
    const float* W_v     = (const float*)d_in[3];
    const float* b_v     = (const float*)d_in[4];
    const float* gamma   = (const float*)d_in[5];
    const float* beta    = (const float*)d_in[6];
    float* out = (float*)d_out;

    k_split<<<16384, 256>>>(feature);
    k_wsplit<<<768, 256>>>(W_qk, W_v);
    k_mma<<<dim3(6, 512), 256>>>(0, b_qk, b_v, nullptr);      // QKV
    k_stats1<<<dim3(NCHUNK, 64), 256>>>();
    k_stats2<<<8, 256>>>();
    k_normT<<<dim3(128, 8, 8), 256>>>();
    k_vT<<<dim3(128, 8, 8), 256>>>();
    k_mma<<<dim3(2, 2, BB*NSPLIT), 256>>>(2, nullptr, nullptr, nullptr);  // lam
    k_red<<<512, 256>>>();
    k_bnstat<<<256, 256>>>(gamma, beta);
    k_bnT<<<dim3(8, 8, 8), dim3(32, 8)>>>();
    k_mma<<<dim3(2, 512), 256>>>(1, nullptr, nullptr, out);   // out
}

// round 6
// speedup vs baseline: 2.0091x; 1.0236x over previous
#include <cuda_runtime.h>
#include <cuda_bf16.h>
#include <cstdint>

#define BB 8
#define NN 8192
#define DD 256
#define NSPLIT 16
#define NCHUNK 32          // k_stats row chunks (8192/256)
#define TOTROWS (BB*NN)    // 65536

// ---------------- scratch globals ------------------------------------------
__device__ float g_K[TOTROWS*DD];                 // fp32 K logits
__device__ float g_V[TOTROWS*DD];                 // fp32 V
__device__ __nv_bfloat16 g_Fhi[TOTROWS*DD];
__device__ __nv_bfloat16 g_Flo[TOTROWS*DD];
__device__ __nv_bfloat16 g_Qhi[TOTROWS*DD];
__device__ __nv_bfloat16 g_Qlo[TOTROWS*DD];
__device__ __nv_bfloat16 g_Wthi[768*DD];
__device__ __nv_bfloat16 g_Wtlo[768*DD];
__device__ __nv_bfloat16 g_Pthi[BB*DD*NN];        // P transposed [b][d][n]
__device__ __nv_bfloat16 g_Ptlo[BB*DD*NN];
__device__ __nv_bfloat16 g_Vthi[BB*DD*NN];        // V transposed [b][e][n]
__device__ __nv_bfloat16 g_Vtlo[BB*DD*NN];
__device__ __nv_bfloat16 g_bnThi[BB*DD*DD];       // bn transposed [b][e][d]
__device__ __nv_bfloat16 g_bnTlo[BB*DD*DD];
__device__ float g_pmax[NCHUNK*BB*DD];
__device__ float g_psum[NCHUNK*BB*DD];
__device__ float g_colmax[BB*DD];
__device__ float g_colrcp[BB*DD];
__device__ float g_lampart[NSPLIT*BB*DD*DD];
__device__ float g_lam[BB*DD*DD];
__device__ float g_scale[DD];
__device__ float g_shift[DD];

// ---------------- helpers --------------------------------------------------
__device__ __forceinline__ uint32_t smem_to_u32(const void* p) {
    uint32_t a;
    asm("{ .reg .u64 t; cvta.to.shared.u64 t, %1; cvt.u32.u64 %0, t; }" : "=r"(a) : "l"(p));
    return a;
}
#define LDSM4(R, addr) \
    asm volatile("ldmatrix.sync.aligned.m8n8.x4.shared.b16 {%0,%1,%2,%3}, [%4];" \
        : "=r"((R)[0]), "=r"((R)[1]), "=r"((R)[2]), "=r"((R)[3]) : "r"(addr))
#define LDSM2(R, addr) \
    asm volatile("ldmatrix.sync.aligned.m8n8.x2.shared.b16 {%0,%1}, [%2];" \
        : "=r"((R)[0]), "=r"((R)[1]) : "r"(addr))
#define CP16(smaddr, gptr) \
    asm volatile("cp.async.cg.shared.global [%0], [%1], 16;" \
        :: "r"((uint32_t)(smaddr)), "l"(gptr))
#define CP_COMMIT() asm volatile("cp.async.commit_group;" ::: "memory")
#define CP_WAIT1()  asm volatile("cp.async.wait_group 1;" ::: "memory")
#define CP_WAIT0()  asm volatile("cp.async.wait_group 0;" ::: "memory")

__device__ __forceinline__ void mma_bf16(float* c, const uint32_t* a, const uint32_t* b) {
    asm volatile("mma.sync.aligned.m16n8k16.row.col.f32.bf16.bf16.f32 "
        "{%0,%1,%2,%3}, {%4,%5,%6,%7}, {%8,%9}, {%0,%1,%2,%3};"
        : "+f"(c[0]), "+f"(c[1]), "+f"(c[2]), "+f"(c[3])
        : "r"(a[0]), "r"(a[1]), "r"(a[2]), "r"(a[3]), "r"(b[0]), "r"(b[1]));
}

__device__ __forceinline__ float fexp(float x) {
    float y = x * 1.4426950408889634f;
    y = fmaxf(y, -126.0f);
    float r = rintf(y);
    float t = (y - r) * 0.6931471805599453f;
    float p = 1.3888889e-3f;
    p = fmaf(p, t, 8.3333333e-3f);
    p = fmaf(p, t, 4.1666667e-2f);
    p = fmaf(p, t, 1.6666667e-1f);
    p = fmaf(p, t, 0.5f);
    p = fmaf(p, t, 1.0f);
    p = fmaf(p, t, 1.0f);
    float sc = __int_as_float(((int)r + 127) << 23);
    return p * sc;
}
__device__ __forceinline__ void split2(float v, __nv_bfloat16& h, __nv_bfloat16& l) {
    h = __float2bfloat16(v);
    l = __float2bfloat16(v - __bfloat162float(h));
}

// ---------------- feature split --------------------------------------------
__global__ __launch_bounds__(256) void k_split(const float* __restrict__ X)
{
    int t = blockIdx.x * 256 + threadIdx.x;
    float4 v = *(const float4*)&X[t * 4];
    __nv_bfloat16 h[4], l[4];
    split2(v.x, h[0], l[0]); split2(v.y, h[1], l[1]);
    split2(v.z, h[2], l[2]); split2(v.w, h[3], l[3]);
    *(uint2*)&g_Fhi[t * 4] = *(uint2*)h;
    *(uint2*)&g_Flo[t * 4] = *(uint2*)l;
}

// ---------------- W transpose + split --------------------------------------
__global__ __launch_bounds__(256) void k_wsplit(const float* __restrict__ Wqk,
                                               const float* __restrict__ Wv)
{
    int n = blockIdx.x;
    int k = threadIdx.x;
    int sec = n >> 8, nn = n & 255;
    float w = (sec == 0) ? Wqk[k * 256 + nn]
            : (sec == 1) ? Wqk[65536 + k * 256 + nn]
                         : Wv[k * 256 + nn];
    __nv_bfloat16 h, l; split2(w, h, l);
    g_Wthi[n * 256 + k] = h;
    g_Wtlo[n * 256 + k] = l;
}

// ---------------- shared MMA GEMM kernel (cp.async double-buffered) --------
// mode 0: C[65536x768] = F @ Wt^T  -> scatter Q(split)/K/V (+bias)
// mode 1: C[65536x256] = Q @ bnT^T -> fp32 out
// mode 2: lam partials: C[256x256] = Pt @ Vt^T over 512-seq split
#define ROWB 80
#define BUFB (128*ROWB)          // 10240 bytes per operand buffer
#define STAGEB (4*BUFB)          // 40960 bytes per stage
#define SMEM_MMA (2*STAGEB)      // 81920 bytes

__global__ __launch_bounds__(256) void k_mma(int mode, const float* __restrict__ bqk,
                                             const float* __restrict__ bv,
                                             float* __restrict__ outp)
{
    extern __shared__ __align__(16) unsigned char sm[];
    int tid = threadIdx.x, lane = tid & 31, wid = tid >> 5;
    int wm = wid >> 2, wn = wid & 3;

    const __nv_bfloat16 *Ah, *Al, *Bh, *Bl;
    long astr, bstr;
    int m0, ncol0;
    int nk = (mode == 2) ? 16 : 8;
    if (mode == 0) {
        ncol0 = blockIdx.x * 128; m0 = blockIdx.y * 128;
        Ah = g_Fhi + (long)m0 * 256;  Al = g_Flo + (long)m0 * 256;
        Bh = g_Wthi + (long)ncol0 * 256; Bl = g_Wtlo + (long)ncol0 * 256;
        astr = bstr = 256;
    } else if (mode == 1) {
        ncol0 = blockIdx.x * 128; m0 = blockIdx.y * 128;
        int b = m0 >> 13;
        Ah = g_Qhi + (long)m0 * 256;  Al = g_Qlo + (long)m0 * 256;
        Bh = g_bnThi + (long)b * 65536 + (long)ncol0 * 256;
        Bl = g_bnTlo + (long)b * 65536 + (long)ncol0 * 256;
        astr = bstr = 256;
    } else {
        int e0 = blockIdx.x * 128, d0 = blockIdx.y * 128;
        int b = blockIdx.z >> 4, sp = blockIdx.z & 15;
        long ab = (long)(b * 256 + d0) * NN + sp * 512;
        long bb = (long)(b * 256 + e0) * NN + sp * 512;
        Ah = g_Pthi + ab; Al = g_Ptlo + ab;
        Bh = g_Vthi + bb; Bl = g_Vtlo + bb;
        astr = bstr = NN;
        m0 = d0; ncol0 = e0;
    }

    float c[16][4];
    #pragma unroll
    for (int i = 0; i < 16; i++)
        #pragma unroll
        for (int j = 0; j < 4; j++) c[i][j] = 0.f;

    uint32_t smb = smem_to_u32(sm);

    // per-thread load coords (fixed): 2 rows x 1 seg per buffer
    int lrow0 = tid >> 2, lcc = tid & 3;          // rows 0..63
    int lrow1 = lrow0 + 64;                       // rows 64..127

    // ---- chunk loader: issue 8 cp.asyncs into stage st for K-offset kk ----
    auto load_chunk = [&](int kk, int st) {
        uint32_t sb = smb + st * STAGEB;
        #pragma unroll
        for (int buf = 0; buf < 4; buf++) {
            const __nv_bfloat16* src = (buf == 0) ? Ah : (buf == 1) ? Al
                                     : (buf == 2) ? Bh : Bl;
            long str = (buf < 2) ? astr : bstr;
            CP16(sb + buf * BUFB + lrow0 * ROWB + lcc * 16,
                 src + (long)lrow0 * str + kk + lcc * 8);
            CP16(sb + buf * BUFB + lrow1 * ROWB + lcc * 16,
                 src + (long)lrow1 * str + kk + lcc * 8);
        }
    };

    load_chunk(0, 0);
    CP_COMMIT();

    for (int ch = 0; ch < nk; ch++) {
        int cur = ch & 1;
        if (ch + 1 < nk) { load_chunk((ch + 1) * 32, cur ^ 1); CP_COMMIT(); }
        if (ch + 1 < nk) { CP_WAIT1(); } else { CP_WAIT0(); }
        __syncthreads();

        uint32_t sb = smb + cur * STAGEB;
        #pragma unroll
        for (int k0 = 0; k0 < 2; k0++) {
            uint32_t a_h[4][4], a_l[4][4], b_h[4][2], b_l[4][2];
            #pragma unroll
            for (int mt = 0; mt < 4; mt++) {
                uint32_t ra = sb + (wm*64 + mt*16 + (lane & 15)) * ROWB
                            + (k0*16 + (lane >> 4) * 8) * 2;
                LDSM4(a_h[mt], ra);
                LDSM4(a_l[mt], ra + BUFB);
            }
            #pragma unroll
            for (int nt = 0; nt < 4; nt++) {
                uint32_t rb = sb + 2*BUFB + (wn*32 + nt*8 + (lane & 7)) * ROWB
                            + (k0*16 + ((lane >> 3) & 1) * 8) * 2;
                LDSM2(b_h[nt], rb);
                LDSM2(b_l[nt], rb + BUFB);
            }
            #pragma unroll
            for (int mt = 0; mt < 4; mt++)
                #pragma unroll
                for (int nt = 0; nt < 4; nt++) {
                    mma_bf16(c[mt*4+nt], a_h[mt], b_h[nt]);
                    mma_bf16(c[mt*4+nt], a_h[mt], b_l[nt]);
                    mma_bf16(c[mt*4+nt], a_l[mt], b_h[nt]);
                }
        }
        __syncthreads();
    }

    // epilogue
    int rbase = m0 + wm * 64;
    int cl0 = wn * 32;
    #pragma unroll
    for (int mt = 0; mt < 4; mt++) {
        #pragma unroll
        for (int nt = 0; nt < 4; nt++) {
            float* cc = c[mt*4+nt];
            int r0 = rbase + mt*16 + (lane >> 2);
            int cl = cl0 + nt*8 + (lane & 3)*2;
            if (mode == 1) {
                float2 v0 = {cc[0], cc[1]}, v1 = {cc[2], cc[3]};
                *(float2*)&outp[(long)r0 * 256 + ncol0 + cl] = v0;
                *(float2*)&outp[(long)(r0+8) * 256 + ncol0 + cl] = v1;
            } else if (mode == 2) {
                int sp = blockIdx.z & 15;
                int b = blockIdx.z >> 4;
                float* op = g_lampart + (long)sp * (BB*DD*DD) + (long)b * 65536;
                float2 v0 = {cc[0], cc[1]}, v1 = {cc[2], cc[3]};
                *(float2*)&op[(long)r0 * 256 + ncol0 + cl] = v0;
                *(float2*)&op[(long)(r0+8) * 256 + ncol0 + cl] = v1;
            } else {
                int sec = ncol0 >> 8;
                int cg = (ncol0 & 255) + cl;
                if (sec == 0) {
                    float b0 = bqk[cg], b1 = bqk[cg+1];
                    #pragma unroll
                    for (int hrow = 0; hrow < 2; hrow++) {
                        int r = r0 + hrow * 8;
                        float v0 = cc[hrow*2+0] + b0, v1 = cc[hrow*2+1] + b1;
                        __nv_bfloat16 h0,l0,h1,l1;
                        split2(v0,h0,l0); split2(v1,h1,l1);
                        __nv_bfloat162 ph; ph.x = h0; ph.y = h1;
                        __nv_bfloat162 pl; pl.x = l0; pl.y = l1;
                        *(__nv_bfloat162*)&g_Qhi[(long)r*256 + cg] = ph;
                        *(__nv_bfloat162*)&g_Qlo[(long)r*256 + cg] = pl;
                    }
                } else {
                    const float* bb = (sec == 1) ? bqk + 256 : bv;
                    float* dst = (sec == 1) ? g_K : g_V;
                    float b0 = bb[cg], b1 = bb[cg+1];
                    float2 v0 = {cc[0] + b0, cc[1] + b1};
                    float2 v1 = {cc[2] + b0, cc[3] + b1};
                    *(float2*)&dst[(long)r0 * 256 + cg] = v0;
                    *(float2*)&dst[(long)(r0+8) * 256 + cg] = v1;
                }
            }
        }
    }
}

// ---------------- softmax stats phase A: per-chunk partials ----------------
__global__ __launch_bounds__(256) void k_stats1()
{
    int ch = blockIdx.x;
    int b  = blockIdx.y >> 3;
    int d0 = (blockIdx.y & 7) << 5;
    int dd = threadIdx.x & 31;
    int g  = threadIdx.x >> 5;
    int d  = d0 + dd;
    const float* base = g_K + ((long)b * NN + ch * 256) * 256 + d;

    float m = -1e30f, s = 0.f;
    #pragma unroll 4
    for (int n = g; n < 256; n += 8) {
        float x = base[(long)n * 256];
        float nm = fmaxf(m, x);
        s = fmaf(s, fexp(m - nm), fexp(x - nm));
        m = nm;
    }
    __shared__ float sm[8][32], ss[8][32];
    sm[g][dd] = m; ss[g][dd] = s;
    __syncthreads();
    if (g == 0) {
        float M = sm[0][dd], S = ss[0][dd];
        #pragma unroll
        for (int i = 1; i < 8; i++) {
            float m2 = sm[i][dd], s2 = ss[i][dd];
            float nm = fmaxf(M, m2);
            S = S * fexp(M - nm) + s2 * fexp(m2 - nm);
            M = nm;
        }
        g_pmax[ch * (BB*DD) + b * 256 + d] = M;
        g_psum[ch * (BB*DD) + b * 256 + d] = S;
    }
}

// ---------------- phase B: combine chunk partials --------------------------
__global__ __launch_bounds__(256) void k_stats2()
{
    int t = blockIdx.x * 256 + threadIdx.x;
    if (t >= BB*DD) return;
    float M = g_pmax[t], S = g_psum[t];
    #pragma unroll
    for (int i = 1; i < NCHUNK; i++) {
        float m2 = g_pmax[i * (BB*DD) + t], s2 = g_psum[i * (BB*DD) + t];
        float nm = fmaxf(M, m2);
        S = S * fexp(M - nm) + s2 * fexp(m2 - nm);
        M = nm;
    }
    g_colmax[t] = M;
    g_colrcp[t] = 1.0f / S;
}

// ---------------- P transpose: exp-normalize + split -> Pt[b][d][n] --------
__global__ __launch_bounds__(256) void k_normT()
{
    __shared__ float tile[64][33];
    int b = blockIdx.z, d0 = blockIdx.y * 32, n0 = blockIdx.x * 64;
    int lx = threadIdx.x & 31, ly = threadIdx.x >> 5;
    float mx = g_colmax[b * 256 + d0 + lx];
    float rc = g_colrcp[b * 256 + d0 + lx];
    #pragma unroll
    for (int i = 0; i < 8; i++) {
        int n = ly + i * 8;
        float kv = g_K[((long)b * NN + n0 + n) * 256 + d0 + lx];
        tile[n][lx] = fexp(kv - mx) * rc;
    }
    __syncthreads();
    int sx = threadIdx.x & 63, sy = threadIdx.x >> 6;
    #pragma unroll
    for (int j = 0; j < 8; j++) {
        int dl = sy + j * 4;
        float v = tile[sx][dl];
        __nv_bfloat16 h, l; split2(v, h, l);
        long o = (long)(b * 256 + d0 + dl) * NN + n0 + sx;
        g_Pthi[o] = h; g_Ptlo[o] = l;
    }
}

// ---------------- V transpose + split -> Vt[b][e][n] -----------------------
__global__ __launch_bounds__(256) void k_vT()
{
    __shared__ float tile[64][33];
    int b = blockIdx.z, e0 = blockIdx.y * 32, n0 = blockIdx.x * 64;
    int lx = threadIdx.x & 31, ly = threadIdx.x >> 5;
    #pragma unroll
    for (int i = 0; i < 8; i++) {
        int n = ly + i * 8;
        tile[n][lx] = g_V[((long)b * NN + n0 + n) * 256 + e0 + lx];
    }
    __syncthreads();
    int sx = threadIdx.x & 63, sy = threadIdx.x >> 6;
    #pragma unroll
    for (int j = 0; j < 8; j++) {
        int el = sy + j * 4;
        float v = tile[sx][el];
        __nv_bfloat16 h, l; split2(v, h, l);
        long o = (long)(b * 256 + e0 + el) * NN + n0 + sx;
        g_Vthi[o] = h; g_Vtlo[o] = l;
    }
}

// ---------------- reduce split-K -------------------------------------------
__global__ __launch_bounds__(256) void k_red()
{
    int t = blockIdx.x * 256 + threadIdx.x;
    float4 a = make_float4(0.f, 0.f, 0.f, 0.f);
    #pragma unroll
    for (int s = 0; s < NSPLIT; s++) {
        float4 v = *(float4*)&g_lampart[(long)s * (BB*DD*DD) + t * 4];
        a.x += v.x; a.y += v.y; a.z += v.z; a.w += v.w;
    }
    *(float4*)&g_lam[t * 4] = a;
}

// ---------------- BN stats per d -------------------------------------------
__global__ __launch_bounds__(256) void k_bnstat(const float* __restrict__ gamma,
                                               const float* __restrict__ beta)
{
    int d = blockIdx.x;
    int tid = threadIdx.x;
    float sum = 0.f, sq = 0.f;
    #pragma unroll
    for (int i = 0; i < 8; i++) {
        int f = tid + i * 256;
        int b = f >> 8, e = f & 255;
        float v = g_lam[(b * 256 + d) * 256 + e];
        sum += v; sq = fmaf(v, v, sq);
    }
    __shared__ float s1[256], s2[256];
    s1[tid] = sum; s2[tid] = sq;
    __syncthreads();
    for (int st = 128; st > 0; st >>= 1) {
        if (tid < st) { s1[tid] += s1[tid+st]; s2[tid] += s2[tid+st]; }
        __syncthreads();
    }
    if (tid == 0) {
        float mean = s1[0] * (1.0f / 2048.0f);
        float var  = s2[0] * (1.0f / 2048.0f) - mean * mean;
        float rstd = rsqrtf(var + 1e-5f);
        float sc = rstd * gamma[d];
        g_scale[d] = sc;
        g_shift[d] = beta[d] - mean * sc;
    }
}

// ---------------- bnT = transpose(BN(lam)), split --------------------------
__global__ void k_bnT()
{
    __shared__ float tile[32][33];
    int b = blockIdx.z, dt = blockIdx.y * 32, et = blockIdx.x * 32;
    int tx = threadIdx.x, ty = threadIdx.y;
    #pragma unroll
    for (int i = 0; i < 4; i++) {
        int d = dt + ty + i * 8;
        float sc = g_scale[d], sh = g_shift[d];
        tile[ty + i * 8][tx] = fmaf(g_lam[(b * 256 + d) * 256 + et + tx], sc, sh);
    }
    __syncthreads();
    #pragma unroll
    for (int i = 0; i < 4; i++) {
        int e = et + ty + i * 8;
        float v = tile[tx][ty + i * 8];
        int o = (b * 256 + e) * 256 + dt + tx;
        __nv_bfloat16 h, l; split2(v, h, l);
        g_bnThi[o] = h; g_bnTlo[o] = l;
    }
}

// ---------------- launch ---------------------------------------------------
extern "C" void kernel_launch(void* const* d_in, const int* in_sizes, int n_in,
                              void* d_out, int out_size)
{
    const float* feature = (const float*)d_in[0];
    const float* W_qk    = (const float*)d_in[1];
    const float* b_qk    = (const float*)d_in[2];
    const float* W_v     = (const float*)d_in[3];
    const float* b_v     = (const float*)d_in[4];
    const float* gamma   = (const float*)d_in[5];
    const float* beta    = (const float*)d_in[6];
    float* out = (float*)d_out;

    cudaFuncSetAttribute(k_mma, cudaFuncAttributeMaxDynamicSharedMemorySize,
                         SMEM_MMA);

    k_split<<<16384, 256>>>(feature);
    k_wsplit<<<768, 256>>>(W_qk, W_v);
    k_mma<<<dim3(6, 512), 256, SMEM_MMA>>>(0, b_qk, b_v, nullptr);      // QKV
    k_stats1<<<dim3(NCHUNK, 64), 256>>>();
    k_stats2<<<8, 256>>>();
    k_normT<<<dim3(128, 8, 8), 256>>>();
    k_vT<<<dim3(128, 8, 8), 256>>>();
    k_mma<<<dim3(2, 2, BB*NSPLIT), 256, SMEM_MMA>>>(2, nullptr, nullptr, nullptr);
    k_red<<<512, 256>>>();
    k_bnstat<<<256, 256>>>(gamma, beta);
    k_bnT<<<dim3(8, 8, 8), dim3(32, 8)>>>();
    k_mma<<<dim3(2, 512), 256, SMEM_MMA>>>(1, nullptr, nullptr, out);   // out
}